// round 10
// baseline (speedup 1.0000x reference)
#include <cuda_runtime.h>

// Problem constants
#define Bb 32
#define Kk 1024
#define Cc 64
#define Oo 32
#define Ii 32

#define QS   32767.0f          // int16 quant scale
#define QSI  (1.0f / 32767.0f)

// ---------------- device scratch (no allocations allowed) ----------------
__device__ unsigned int g_uh[(size_t)Bb * Kk * Cc * Oo / 2]; // int16x2, 134 MB
__device__ float g_b1[Bb * Kk * Cc];                         // 8 MB
__device__ float g_s0[Bb * Cc * Oo];
__device__ float g_s1[Bb * Cc * Oo];
__device__ float g_s2[Bb * Cc * Oo];
__device__ float g_v0[Bb * Cc * Oo];
__device__ float g_v1[Bb * Cc * Oo];

// ---------------- helpers ------------------------------------------------
__device__ __forceinline__ unsigned int to_tf32(float f) {
    unsigned int r;
    asm("cvt.rna.tf32.f32 %0, %1;" : "=r"(r) : "f"(f));
    return r;
}
__device__ __forceinline__ void mma_tf32(float acc[4],
        unsigned int a0, unsigned int a1, unsigned int a2, unsigned int a3,
        unsigned int b0, unsigned int b1) {
    asm("mma.sync.aligned.m16n8k8.row.col.f32.tf32.tf32.f32 "
        "{%0,%1,%2,%3}, {%4,%5,%6,%7}, {%8,%9}, {%0,%1,%2,%3};"
        : "+f"(acc[0]), "+f"(acc[1]), "+f"(acc[2]), "+f"(acc[3])
        : "r"(a0), "r"(a1), "r"(a2), "r"(a3), "r"(b0), "r"(b1));
}
__device__ __forceinline__ unsigned int packq(float a, float b) {
    int ia = __float2int_rn(a * QS);   // |u_hat| << 1: no clamp needed
    int ib = __float2int_rn(b * QS);
    return (unsigned int)(ia & 0xffff) | ((unsigned int)ib << 16);
}
__device__ __forceinline__ void unpack8(uint4 uv, float* uh) {
    uh[0] = (float)((short)(uv.x & 0xffff)); uh[1] = (float)((short)(uv.x >> 16));
    uh[2] = (float)((short)(uv.y & 0xffff)); uh[3] = (float)((short)(uv.y >> 16));
    uh[4] = (float)((short)(uv.z & 0xffff)); uh[5] = (float)((short)(uv.z >> 16));
    uh[6] = (float)((short)(uv.w & 0xffff)); uh[7] = (float)((short)(uv.w >> 16));
}
__device__ __forceinline__ void cpa16(void* dst, const void* src) {
    unsigned int d = (unsigned int)__cvta_generic_to_shared(dst);
    asm volatile("cp.async.cg.shared.global [%0], [%1], 16;"
                 :: "r"(d), "l"(src) : "memory");
}
__device__ __forceinline__ void cp_commit() {
    asm volatile("cp.async.commit_group;" ::: "memory");
}
template <int N> __device__ __forceinline__ void cp_wait() {
    asm volatile("cp.async.wait_group %0;" :: "n"(N) : "memory");
}
__device__ __forceinline__ void cp_wait_all() {
    asm volatile("cp.async.wait_all;" ::: "memory");
}

// ---------------- zero accumulators (graph replays!) ---------------------
__global__ void zero_s_kernel() {
    int i = blockIdx.x * 256 + threadIdx.x;
    if (i < Bb * Cc * Oo) { g_s0[i] = 0.f; g_s1[i] = 0.f; g_s2[i] = 0.f; }
}

// ---------------- Pass 1: u_hat tf32 mma, cp.async double-buffered -------
// grid=(Kk/KPB, 8 c-eighths), 256 thr. W tile k+1 streams while k computes.
#define KPB 8
#define SP 36                    // smem row stride in words
#define WELE (256 * SP)          // one W buffer (floats)
#define XELE (32 * SP)           // one x buffer
#define UHAT_SMEM ((2 * WELE + 2 * XELE) * 4)   // 82,944 B

__global__ void __launch_bounds__(256)
uhat_tf32_kernel(const float* __restrict__ x, const float* __restrict__ W) {
    extern __shared__ float dsm[];
    float* Wb0 = dsm;
    float* Wb1 = dsm + WELE;
    float* Xb0 = dsm + 2 * WELE;
    float* Xb1 = dsm + 2 * WELE + XELE;

    const int t = threadIdx.x, lane = t & 31, w = t >> 5;
    const int g = lane >> 2, tg = lane & 3;
    const int q  = blockIdx.y;          // c-eighth
    const int k0 = blockIdx.x * KPB;
    const int c  = q * 8 + w;           // this warp's class

    auto stage = [&](int k, float* Wd, float* Xd) {
        const float4* wg = reinterpret_cast<const float4*>(
            W + ((size_t)k * Cc + q * 8) * (Oo * Ii));
#pragma unroll
        for (int it = 0; it < 8; it++) {
            int p = it * 256 + t, m = p >> 3, j = p & 7;
            cpa16(&Wd[m * SP + 4 * j], wg + p);
        }
        const float4* xg = reinterpret_cast<const float4*>(x);
        int bb = t >> 3, j = t & 7;
        cpa16(&Xd[bb * SP + 4 * j], xg + ((size_t)bb * Kk + k) * 8 + j);
        cp_commit();
    };

    float s0acc[32];
#pragma unroll
    for (int i = 0; i < 32; i++) s0acc[i] = 0.f;

    stage(k0, Wb0, Xb0);

#pragma unroll
    for (int kk = 0; kk < KPB; kk++) {
        const int k = k0 + kk;
        const int cur = kk & 1;
        if (kk + 1 < KPB) {
            stage(k + 1, cur ? Wb0 : Wb1, cur ? Xb0 : Xb1);
            cp_wait<1>();
        } else {
            cp_wait<0>();
        }
        __syncthreads();
        const float* Wc = cur ? Wb1 : Wb0;
        const float* Xc = cur ? Xb1 : Xb0;

        // W (B-operand) fragments, cvt at load; shared by both m-tiles
        unsigned int wf[4][4][2];
#pragma unroll
        for (int j = 0; j < 4; j++) {
            const int n0 = w * 32 + j * 8;
#pragma unroll
            for (int ks = 0; ks < 4; ks++) {
                wf[j][ks][0] = to_tf32(Wc[(n0 + g) * SP + ks * 8 + tg]);
                wf[j][ks][1] = to_tf32(Wc[(n0 + g) * SP + ks * 8 + tg + 4]);
            }
        }

#pragma unroll
        for (int mt = 0; mt < 2; mt++) {
            const int mb = mt * 16;
            unsigned int af[4][4];
#pragma unroll
            for (int ks = 0; ks < 4; ks++) {
                af[ks][0] = to_tf32(Xc[(mb + g)     * SP + ks * 8 + tg]);
                af[ks][1] = to_tf32(Xc[(mb + g + 8) * SP + ks * 8 + tg]);
                af[ks][2] = to_tf32(Xc[(mb + g)     * SP + ks * 8 + tg + 4]);
                af[ks][3] = to_tf32(Xc[(mb + g + 8) * SP + ks * 8 + tg + 4]);
            }
#pragma unroll
            for (int j = 0; j < 4; j++) {
                float acc[4] = {0.f, 0.f, 0.f, 0.f};
#pragma unroll
                for (int ks = 0; ks < 4; ks++)
                    mma_tf32(acc, af[ks][0], af[ks][1], af[ks][2], af[ks][3],
                             wf[j][ks][0], wf[j][ks][1]);
                s0acc[(mt * 4 + j) * 4 + 0] += acc[0];
                s0acc[(mt * 4 + j) * 4 + 1] += acc[1];
                s0acc[(mt * 4 + j) * 4 + 2] += acc[2];
                s0acc[(mt * 4 + j) * 4 + 3] += acc[3];
                const int ba = mb + g, bb2 = mb + g + 8;
                size_t ia = (((size_t)ba  * Kk + k) * Cc + c) * 16 + 4 * j + tg;
                size_t ib = (((size_t)bb2 * Kk + k) * Cc + c) * 16 + 4 * j + tg;
                g_uh[ia] = packq(acc[0], acc[1]);
                g_uh[ib] = packq(acc[2], acc[3]);
            }
        }
        __syncthreads();   // all warps done with cur buffers before re-stage
    }

    // flush s0 partials
#pragma unroll
    for (int mt = 0; mt < 2; mt++)
#pragma unroll
        for (int j = 0; j < 4; j++) {
            int ba = mt * 16 + g, bb2 = ba + 8, o = 8 * j + 2 * tg;
            atomicAdd(&g_s0[(ba  * Cc + c) * Oo + o],     s0acc[(mt*4+j)*4 + 0]);
            atomicAdd(&g_s0[(ba  * Cc + c) * Oo + o + 1], s0acc[(mt*4+j)*4 + 1]);
            atomicAdd(&g_s0[(bb2 * Cc + c) * Oo + o],     s0acc[(mt*4+j)*4 + 2]);
            atomicAdd(&g_s0[(bb2 * Cc + c) * Oo + o + 1], s0acc[(mt*4+j)*4 + 3]);
        }
}

// ---------------- squash -------------------------------------------------
__global__ void squash_kernel(int which, float* __restrict__ ext_out) {
    const float* s = (which == 0) ? g_s0 : (which == 1) ? g_s1 : g_s2;
    float* vout    = (which == 0) ? g_v0 : (which == 1) ? g_v1 : ext_out;
    const float scale = (which == 0) ? (1.0f / Cc) : 1.0f;

    int lane = threadIdx.x & 31, w = threadIdx.x >> 5;
    int row  = blockIdx.x * 8 + w;
    float val = s[row * 32 + lane] * scale;
    float sq = val * val;
#pragma unroll
    for (int sh = 16; sh > 0; sh >>= 1) sq += __shfl_xor_sync(~0u, sq, sh);
    float f = (sq / (1.0f + sq)) * rsqrtf(sq + 1e-8f);
    vout[row * 32 + lane] = val * f;
}

// ---------------- routing pass: smem-resident tile via cp.async ----------
// Thread t copies & consumes exactly its own 16B per k (c=t>>2, oh=t&3).
// A: agreements from smem. B: warp w softmaxes k=w. C: s-accum from smem.
#define KC3 8
__global__ void __launch_bounds__(256)
route3_kernel(int iter, float* __restrict__ c_out_ext) {
    __shared__ uint4 tile[KC3][256];      // 32 KB (u_hat tile, int16x2)
    __shared__ float tbs[KC3][Cc];        // 2 KB
    __shared__ float csm[KC3][Cc];        // 2 KB

    const int t = threadIdx.x, lane = t & 31, w = t >> 5;
    const int c  = t >> 2;                // = 8w + (lane>>2)
    const int oh = t & 3;
    const int b  = blockIdx.y;
    const int k0 = blockIdx.x * KC3;

    const float* v = iter ? g_v1 : g_v0;
    float* s_out   = iter ? g_s2 : g_s1;

    // issue the whole 32 KB tile (thread t: its own 16B per k)
#pragma unroll
    for (int kk = 0; kk < KC3; kk++)
        cpa16(&tile[kk][t],
              g_uh + ((size_t)b * Kk + k0 + kk) * (Cc * 16) + t * 4);
    cp_commit();

    // v while copies are in flight (32B/thread, coalesced)
    const float* vp = v + ((size_t)(b * Cc + c)) * Oo + oh * 8;
    float4 va = *reinterpret_cast<const float4*>(vp);
    float4 vb = *reinterpret_cast<const float4*>(vp + 4);
    float vvs[8] = { va.x * QSI, va.y * QSI, va.z * QSI, va.w * QSI,
                     vb.x * QSI, vb.y * QSI, vb.z * QSI, vb.w * QSI };

    cp_wait_all();   // own copies done; phase A reads only own bytes

    // ---- Phase A: agreements ----
#pragma unroll
    for (int kk = 0; kk < KC3; kk++) {
        float uh[8];
        unpack8(tile[kk][t], uh);
        float ap = 0.f;
#pragma unroll
        for (int j = 0; j < 8; j++) ap = fmaf(uh[j], vvs[j], ap);
        ap += __shfl_xor_sync(~0u, ap, 1);
        ap += __shfl_xor_sync(~0u, ap, 2);       // full sum over o
        if (oh == 0) tbs[kk][c] = ap;
    }
    __syncthreads();

    // ---- Phase B: softmax, warp w handles k = w ----
    {
        const size_t bk = (size_t)b * Kk + k0 + w;
        float tA = tbs[w][lane], tB = tbs[w][lane + 32];
        if (iter) {
            tA += g_b1[bk * Cc + lane];
            tB += g_b1[bk * Cc + lane + 32];
        }
        float eA = __expf(tA), eB = __expf(tB);  // |t| << 1: no max-pass
        float s = eA + eB;
#pragma unroll
        for (int sh = 16; sh > 0; sh >>= 1) s += __shfl_xor_sync(~0u, s, sh);
        float inv = 1.0f / s;                    // exact sum over 64 classes
        float cvA = eA * inv, cvB = eB * inv;
        csm[w][lane]      = cvA;
        csm[w][lane + 32] = cvB;
        if (iter) {
            c_out_ext[bk * Cc + lane]      = cvA;
            c_out_ext[bk * Cc + lane + 32] = cvB;
        } else {
            g_b1[bk * Cc + lane]      = tA;
            g_b1[bk * Cc + lane + 32] = tB;
        }
    }
    __syncthreads();

    // ---- Phase C: s accumulation from smem ----
    float sacc[8];
#pragma unroll
    for (int j = 0; j < 8; j++) sacc[j] = 0.f;
#pragma unroll
    for (int kk = 0; kk < KC3; kk++) {
        float uh[8];
        unpack8(tile[kk][t], uh);
        float cij = csm[kk][c];
#pragma unroll
        for (int j = 0; j < 8; j++) sacc[j] = fmaf(cij, uh[j], sacc[j]);
    }

#pragma unroll
    for (int j = 0; j < 8; j++)
        atomicAdd(&s_out[(b * Cc + c) * Oo + oh * 8 + j], sacc[j] * QSI);
}

// ---------------- launch -------------------------------------------------
extern "C" void kernel_launch(void* const* d_in, const int* in_sizes, int n_in,
                              void* d_out, int out_size) {
    const float* x = (const float*)d_in[0];   // [B,K,I]
    const float* W = (const float*)d_in[1];   // [K,C,O,I]
    if (n_in >= 2 && in_sizes[0] > in_sizes[1]) {  // defensive: order by size
        const float* tmp = x; x = W; W = tmp;
    }
    float* out   = (float*)d_out;
    float* v_out = out;                 // [B,C,O]
    float* c_out = out + Bb * Cc * Oo;  // [B,K,C]

    // opt-in to >48KB dynamic smem (host-side attr set; not a stream op)
    cudaFuncSetAttribute(uhat_tf32_kernel,
                         cudaFuncAttributeMaxDynamicSharedMemorySize, UHAT_SMEM);

    zero_s_kernel<<<(Bb * Cc * Oo + 255) / 256, 256>>>();

    uhat_tf32_kernel<<<dim3(Kk / KPB, 8), 256, UHAT_SMEM>>>(x, W);

    squash_kernel<<<(Bb * Cc) / 8, 256>>>(0, nullptr);   // v0 = squash(s0/C)

    route3_kernel<<<dim3(Kk / KC3, Bb), 256>>>(0, nullptr); // b1, s1
    squash_kernel<<<(Bb * Cc) / 8, 256>>>(1, nullptr);      // v1

    route3_kernel<<<dim3(Kk / KC3, Bb), 256>>>(1, c_out);   // c_ij out, s2
    squash_kernel<<<(Bb * Cc) / 8, 256>>>(2, v_out);        // v out
}

// round 11
// speedup vs baseline: 1.6639x; 1.6639x over previous
#include <cuda_runtime.h>

// Problem constants
#define Bb 32
#define Kk 1024
#define Cc 64
#define Oo 32
#define Ii 32

#define QS   32767.0f          // int16 quant scale
#define QSI  (1.0f / 32767.0f)

#define NKB0 128               // uhat k-blocks (Kk/KPB)
#define NKB1 64                // route k-blocks (Kk/KC2)

// ---------------- device scratch (no allocations allowed) ----------------
__device__ unsigned int g_uh[(size_t)Bb * Kk * Cc * Oo / 2]; // int16x2, 134 MB
__device__ float g_b1[Bb * Kk * Cc];                         // 8 MB
__device__ float g_p0[(size_t)NKB0 * Bb * Cc * Oo];          // 32 MB s0 partials
__device__ float g_p1[(size_t)NKB1 * Bb * Cc * Oo];          // 16 MB s1/s2 partials
__device__ float g_v0[Bb * Cc * Oo];
__device__ float g_v1[Bb * Cc * Oo];

// ---------------- helpers ------------------------------------------------
__device__ __forceinline__ unsigned int to_tf32(float f) {
    unsigned int r;
    asm("cvt.rna.tf32.f32 %0, %1;" : "=r"(r) : "f"(f));
    return r;
}
__device__ __forceinline__ void mma_tf32(float acc[4],
        unsigned int a0, unsigned int a1, unsigned int a2, unsigned int a3,
        unsigned int b0, unsigned int b1) {
    asm("mma.sync.aligned.m16n8k8.row.col.f32.tf32.tf32.f32 "
        "{%0,%1,%2,%3}, {%4,%5,%6,%7}, {%8,%9}, {%0,%1,%2,%3};"
        : "+f"(acc[0]), "+f"(acc[1]), "+f"(acc[2]), "+f"(acc[3])
        : "r"(a0), "r"(a1), "r"(a2), "r"(a3), "r"(b0), "r"(b1));
}
__device__ __forceinline__ unsigned int packq(float a, float b) {
    int ia = __float2int_rn(a * QS);   // |u_hat| << 1: no clamp needed
    int ib = __float2int_rn(b * QS);
    return (unsigned int)(ia & 0xffff) | ((unsigned int)ib << 16);
}
__device__ __forceinline__ void unpack8(uint4 uv, float* uh) {
    uh[0] = (float)((short)(uv.x & 0xffff)); uh[1] = (float)((short)(uv.x >> 16));
    uh[2] = (float)((short)(uv.y & 0xffff)); uh[3] = (float)((short)(uv.y >> 16));
    uh[4] = (float)((short)(uv.z & 0xffff)); uh[5] = (float)((short)(uv.z >> 16));
    uh[6] = (float)((short)(uv.w & 0xffff)); uh[7] = (float)((short)(uv.w >> 16));
}
__device__ __forceinline__ void cpa16(void* dst, const void* src) {
    unsigned int d = (unsigned int)__cvta_generic_to_shared(dst);
    asm volatile("cp.async.cg.shared.global [%0], [%1], 16;"
                 :: "r"(d), "l"(src) : "memory");
}
__device__ __forceinline__ void cp_commit() {
    asm volatile("cp.async.commit_group;" ::: "memory");
}
template <int N> __device__ __forceinline__ void cp_wait() {
    asm volatile("cp.async.wait_group %0;" :: "n"(N) : "memory");
}

// ---------------- Pass 1: u_hat tf32 mma, cp.async double-buffered -------
// grid=(NKB0, 8 c-eighths), 256 thr. s0 partials -> plain stores (no atomics).
#define KPB 8
#define SP 36                    // smem row stride in words
#define WELE (256 * SP)
#define XELE (32 * SP)
#define UHAT_SMEM ((2 * WELE + 2 * XELE) * 4)   // 82,944 B

__global__ void __launch_bounds__(256)
uhat_tf32_kernel(const float* __restrict__ x, const float* __restrict__ W) {
    extern __shared__ float dsm[];
    float* Wb0 = dsm;
    float* Wb1 = dsm + WELE;
    float* Xb0 = dsm + 2 * WELE;
    float* Xb1 = dsm + 2 * WELE + XELE;

    const int t = threadIdx.x, lane = t & 31, w = t >> 5;
    const int g = lane >> 2, tg = lane & 3;
    const int q  = blockIdx.y;          // c-eighth
    const int k0 = blockIdx.x * KPB;
    const int c  = q * 8 + w;           // this warp's class

    auto stage = [&](int k, float* Wd, float* Xd) {
        const float4* wg = reinterpret_cast<const float4*>(
            W + ((size_t)k * Cc + q * 8) * (Oo * Ii));
#pragma unroll
        for (int it = 0; it < 8; it++) {
            int p = it * 256 + t, m = p >> 3, j = p & 7;
            cpa16(&Wd[m * SP + 4 * j], wg + p);
        }
        const float4* xg = reinterpret_cast<const float4*>(x);
        int bb = t >> 3, j = t & 7;
        cpa16(&Xd[bb * SP + 4 * j], xg + ((size_t)bb * Kk + k) * 8 + j);
        cp_commit();
    };

    float s0acc[32];
#pragma unroll
    for (int i = 0; i < 32; i++) s0acc[i] = 0.f;

    stage(k0, Wb0, Xb0);

#pragma unroll
    for (int kk = 0; kk < KPB; kk++) {
        const int k = k0 + kk;
        const int cur = kk & 1;
        if (kk + 1 < KPB) {
            stage(k + 1, cur ? Wb0 : Wb1, cur ? Xb0 : Xb1);
            cp_wait<1>();
        } else {
            cp_wait<0>();
        }
        __syncthreads();
        const float* Wc = cur ? Wb1 : Wb0;
        const float* Xc = cur ? Xb1 : Xb0;

        unsigned int wf[4][4][2];
#pragma unroll
        for (int j = 0; j < 4; j++) {
            const int n0 = w * 32 + j * 8;
#pragma unroll
            for (int ks = 0; ks < 4; ks++) {
                wf[j][ks][0] = to_tf32(Wc[(n0 + g) * SP + ks * 8 + tg]);
                wf[j][ks][1] = to_tf32(Wc[(n0 + g) * SP + ks * 8 + tg + 4]);
            }
        }

#pragma unroll
        for (int mt = 0; mt < 2; mt++) {
            const int mb = mt * 16;
            unsigned int af[4][4];
#pragma unroll
            for (int ks = 0; ks < 4; ks++) {
                af[ks][0] = to_tf32(Xc[(mb + g)     * SP + ks * 8 + tg]);
                af[ks][1] = to_tf32(Xc[(mb + g + 8) * SP + ks * 8 + tg]);
                af[ks][2] = to_tf32(Xc[(mb + g)     * SP + ks * 8 + tg + 4]);
                af[ks][3] = to_tf32(Xc[(mb + g + 8) * SP + ks * 8 + tg + 4]);
            }
#pragma unroll
            for (int j = 0; j < 4; j++) {
                float acc[4] = {0.f, 0.f, 0.f, 0.f};
#pragma unroll
                for (int ks = 0; ks < 4; ks++)
                    mma_tf32(acc, af[ks][0], af[ks][1], af[ks][2], af[ks][3],
                             wf[j][ks][0], wf[j][ks][1]);
                s0acc[(mt * 4 + j) * 4 + 0] += acc[0];
                s0acc[(mt * 4 + j) * 4 + 1] += acc[1];
                s0acc[(mt * 4 + j) * 4 + 2] += acc[2];
                s0acc[(mt * 4 + j) * 4 + 3] += acc[3];
                const int ba = mb + g, bb2 = mb + g + 8;
                size_t ia = (((size_t)ba  * Kk + k) * Cc + c) * 16 + 4 * j + tg;
                size_t ib = (((size_t)bb2 * Kk + k) * Cc + c) * 16 + 4 * j + tg;
                g_uh[ia] = packq(acc[0], acc[1]);
                g_uh[ib] = packq(acc[2], acc[3]);
            }
        }
        __syncthreads();
    }

    // flush s0 partials: plain float2 stores into this k-block's slice
    float* p0 = g_p0 + (size_t)blockIdx.x * (Bb * Cc * Oo);
#pragma unroll
    for (int mt = 0; mt < 2; mt++)
#pragma unroll
        for (int j = 0; j < 4; j++) {
            int ba = mt * 16 + g, bb2 = ba + 8, o = 8 * j + 2 * tg;
            *reinterpret_cast<float2*>(&p0[(ba  * Cc + c) * Oo + o]) =
                make_float2(s0acc[(mt*4+j)*4 + 0], s0acc[(mt*4+j)*4 + 1]);
            *reinterpret_cast<float2*>(&p0[(bb2 * Cc + c) * Oo + o]) =
                make_float2(s0acc[(mt*4+j)*4 + 2], s0acc[(mt*4+j)*4 + 3]);
        }
}

// ---------------- reduce partials + squash (replaces atomics+zero) -------
// warp per (b,c) row; lane = o. which: 0 -> g_p0(128)/scale 1/C -> v0;
// 1 -> g_p1(64) -> v1; 2 -> g_p1(64) -> ext_out.
__global__ void __launch_bounds__(256)
reduce_squash_kernel(int which, float* __restrict__ ext_out) {
    const float* part = (which == 0) ? g_p0 : g_p1;
    const int   NP    = (which == 0) ? NKB0 : NKB1;
    float* vout       = (which == 0) ? g_v0 : (which == 1) ? g_v1 : ext_out;
    const float scale = (which == 0) ? (1.0f / Cc) : 1.0f;

    int lane = threadIdx.x & 31, w = threadIdx.x >> 5;
    size_t idx = (size_t)(blockIdx.x * 8 + w) * 32 + lane;

    float a0 = 0.f, a1 = 0.f, a2 = 0.f, a3 = 0.f;
    for (int p = 0; p < NP; p += 4) {       // 4 independent chains (MLP)
        a0 += part[(size_t)(p)     * (Bb * Cc * Oo) + idx];
        a1 += part[(size_t)(p + 1) * (Bb * Cc * Oo) + idx];
        a2 += part[(size_t)(p + 2) * (Bb * Cc * Oo) + idx];
        a3 += part[(size_t)(p + 3) * (Bb * Cc * Oo) + idx];
    }
    float val = ((a0 + a1) + (a2 + a3)) * scale;

    float sq = val * val;
#pragma unroll
    for (int sh = 16; sh > 0; sh >>= 1) sq += __shfl_xor_sync(~0u, sq, sh);
    float f = (sq / (1.0f + sq)) * rsqrtf(sq + 1e-8f);
    vout[idx] = val * f;
}

// ---------------- routing pass: 3-phase, no atomics ----------------------
// Thread -> (c, oh): c = 8w + (lane>>2), oh = lane&3 (8 o's = 1 uint4).
// A: 16 independent agreement chains. B: warp w softmaxes k=2w,2w+1.
// C: s-accum (L2-hit re-reads) -> plain float4 partial stores.
#define KC2 16
__global__ void __launch_bounds__(256)
route2_kernel(int iter, float* __restrict__ c_out_ext) {
    __shared__ float tbs[KC2][Cc];        // 4 KB
    __shared__ float csm[KC2][Cc];        // 4 KB

    const int t = threadIdx.x, lane = t & 31, w = t >> 5;
    const int c  = w * 8 + (lane >> 2);
    const int oh = lane & 3;
    const int b  = blockIdx.y;
    const int k0 = blockIdx.x * KC2;

    const float* v = iter ? g_v1 : g_v0;

    // v: each thread reads exactly its own 32B (coalesced)
    const float* vp = v + ((size_t)(b * Cc + c)) * Oo + oh * 8;
    float4 va = *reinterpret_cast<const float4*>(vp);
    float4 vb = *reinterpret_cast<const float4*>(vp + 4);
    float vvs[8] = { va.x * QSI, va.y * QSI, va.z * QSI, va.w * QSI,
                     vb.x * QSI, vb.y * QSI, vb.z * QSI, vb.w * QSI };

    // ---- Phase A: agreements (16 independent chains) ----
#pragma unroll
    for (int kk = 0; kk < KC2; kk++) {
        const size_t bk = (size_t)b * Kk + k0 + kk;
        uint4 uv = *reinterpret_cast<const uint4*>(
            &g_uh[(bk * Cc + c) * 16 + oh * 4]);
        float uh[8];
        unpack8(uv, uh);
        float ap = 0.f;
#pragma unroll
        for (int j = 0; j < 8; j++) ap = fmaf(uh[j], vvs[j], ap);
        ap += __shfl_xor_sync(~0u, ap, 1);
        ap += __shfl_xor_sync(~0u, ap, 2);       // full sum over o
        if (oh == 0) tbs[kk][c] = ap;
    }
    __syncthreads();

    // ---- Phase B: softmax, warp w handles k = 2w, 2w+1 ----
#pragma unroll
    for (int h = 0; h < 2; h++) {
        const int kk = 2 * w + h;
        const size_t bk = (size_t)b * Kk + k0 + kk;
        float tA = tbs[kk][lane], tB = tbs[kk][lane + 32];
        if (iter) {
            tA += g_b1[bk * Cc + lane];
            tB += g_b1[bk * Cc + lane + 32];
        }
        float eA = __expf(tA), eB = __expf(tB);  // |t| << 1: no max-pass
        float s = eA + eB;
#pragma unroll
        for (int sh = 16; sh > 0; sh >>= 1) s += __shfl_xor_sync(~0u, s, sh);
        float inv = 1.0f / s;                    // exact sum over 64 classes
        float cvA = eA * inv, cvB = eB * inv;
        csm[kk][lane]      = cvA;
        csm[kk][lane + 32] = cvB;
        if (iter) {
            c_out_ext[bk * Cc + lane]      = cvA;
            c_out_ext[bk * Cc + lane + 32] = cvB;
        } else {
            g_b1[bk * Cc + lane]      = tA;
            g_b1[bk * Cc + lane + 32] = tB;
        }
    }
    __syncthreads();

    // ---- Phase C: s accumulation (independent chains, cached reads) ----
    float sacc[8];
#pragma unroll
    for (int j = 0; j < 8; j++) sacc[j] = 0.f;
#pragma unroll
    for (int kk = 0; kk < KC2; kk++) {
        const size_t bk = (size_t)b * Kk + k0 + kk;
        uint4 uv = *reinterpret_cast<const uint4*>(
            &g_uh[(bk * Cc + c) * 16 + oh * 4]);
        float uh[8];
        unpack8(uv, uh);
        float cij = csm[kk][c];
#pragma unroll
        for (int j = 0; j < 8; j++) sacc[j] = fmaf(cij, uh[j], sacc[j]);
    }

    // plain coalesced partial stores (whole warp = 8192B contiguous)
    float* pd = g_p1 + ((size_t)blockIdx.x * Bb + b) * (Cc * Oo)
              + c * Oo + oh * 8;
    *reinterpret_cast<float4*>(pd) =
        make_float4(sacc[0] * QSI, sacc[1] * QSI, sacc[2] * QSI, sacc[3] * QSI);
    *reinterpret_cast<float4*>(pd + 4) =
        make_float4(sacc[4] * QSI, sacc[5] * QSI, sacc[6] * QSI, sacc[7] * QSI);
}

// ---------------- launch -------------------------------------------------
extern "C" void kernel_launch(void* const* d_in, const int* in_sizes, int n_in,
                              void* d_out, int out_size) {
    const float* x = (const float*)d_in[0];   // [B,K,I]
    const float* W = (const float*)d_in[1];   // [K,C,O,I]
    if (n_in >= 2 && in_sizes[0] > in_sizes[1]) {  // defensive: order by size
        const float* tmp = x; x = W; W = tmp;
    }
    float* out   = (float*)d_out;
    float* v_out = out;                 // [B,C,O]
    float* c_out = out + Bb * Cc * Oo;  // [B,K,C]

    cudaFuncSetAttribute(uhat_tf32_kernel,
                         cudaFuncAttributeMaxDynamicSharedMemorySize, UHAT_SMEM);

    uhat_tf32_kernel<<<dim3(NKB0, 8), 256, UHAT_SMEM>>>(x, W);   // u_hat + p0

    reduce_squash_kernel<<<(Bb * Cc) / 8, 256>>>(0, nullptr);    // v0

    route2_kernel<<<dim3(NKB1, Bb), 256>>>(0, nullptr);          // b1, p1
    reduce_squash_kernel<<<(Bb * Cc) / 8, 256>>>(1, nullptr);    // v1

    route2_kernel<<<dim3(NKB1, Bb), 256>>>(1, c_out);            // c_ij, p1
    reduce_squash_kernel<<<(Bb * Cc) / 8, 256>>>(2, v_out);      // v out
}

// round 12
// speedup vs baseline: 1.6858x; 1.0132x over previous
#include <cuda_runtime.h>

// Problem constants
#define Bb 32
#define Kk 1024
#define Cc 64
#define Oo 32
#define Ii 32

#define QS   32767.0f          // int16 quant scale
#define QSI  (1.0f / 32767.0f)

#define NKB0 128               // uhat k-blocks (Kk/KPB)
#define NKB1 128               // route k-blocks (Kk/KC3)
#define BCO  (Bb * Cc * Oo)    // 65536

// ---------------- device scratch (no allocations allowed) ----------------
__device__ unsigned int g_uh[(size_t)Bb * Kk * Cc * Oo / 2]; // int16x2, 134 MB
__device__ float g_b1[Bb * Kk * Cc];                         // 8 MB
__device__ float g_p0[(size_t)NKB0 * BCO];                   // 32 MB s0 partials
__device__ float g_p1[(size_t)NKB1 * BCO];                   // 32 MB s1/s2 partials
__device__ float g_v0[BCO];
__device__ float g_v1[BCO];

// ---------------- helpers ------------------------------------------------
__device__ __forceinline__ unsigned int to_tf32(float f) {
    unsigned int r;
    asm("cvt.rna.tf32.f32 %0, %1;" : "=r"(r) : "f"(f));
    return r;
}
__device__ __forceinline__ void mma_tf32(float acc[4],
        unsigned int a0, unsigned int a1, unsigned int a2, unsigned int a3,
        unsigned int b0, unsigned int b1) {
    asm("mma.sync.aligned.m16n8k8.row.col.f32.tf32.tf32.f32 "
        "{%0,%1,%2,%3}, {%4,%5,%6,%7}, {%8,%9}, {%0,%1,%2,%3};"
        : "+f"(acc[0]), "+f"(acc[1]), "+f"(acc[2]), "+f"(acc[3])
        : "r"(a0), "r"(a1), "r"(a2), "r"(a3), "r"(b0), "r"(b1));
}
__device__ __forceinline__ unsigned int packq(float a, float b) {
    int ia = __float2int_rn(a * QS);   // |u_hat| << 1: no clamp needed
    int ib = __float2int_rn(b * QS);
    return (unsigned int)(ia & 0xffff) | ((unsigned int)ib << 16);
}
__device__ __forceinline__ void unpack8(uint4 uv, float* uh) {
    uh[0] = (float)((short)(uv.x & 0xffff)); uh[1] = (float)((short)(uv.x >> 16));
    uh[2] = (float)((short)(uv.y & 0xffff)); uh[3] = (float)((short)(uv.y >> 16));
    uh[4] = (float)((short)(uv.z & 0xffff)); uh[5] = (float)((short)(uv.z >> 16));
    uh[6] = (float)((short)(uv.w & 0xffff)); uh[7] = (float)((short)(uv.w >> 16));
}
__device__ __forceinline__ void cpa16(void* dst, const void* src) {
    unsigned int d = (unsigned int)__cvta_generic_to_shared(dst);
    asm volatile("cp.async.cg.shared.global [%0], [%1], 16;"
                 :: "r"(d), "l"(src) : "memory");
}
__device__ __forceinline__ void cp_commit() {
    asm volatile("cp.async.commit_group;" ::: "memory");
}
template <int N> __device__ __forceinline__ void cp_wait() {
    asm volatile("cp.async.wait_group %0;" :: "n"(N) : "memory");
}

// ---------------- Pass 1: u_hat tf32 mma + smem store transpose ----------
// grid=(NKB0, 8 c-eighths), 256 thr. Epilogue: per-k 16KB tile staged in
// padded smem, flushed with fully-coalesced STG.128 (512B/warp contiguous).
#define KPB 8
#define SP 36                    // compute-smem row stride (words)
#define WELE (256 * SP)
#define XELE (32 * SP)
#define UBST 132                 // ubuf row stride (uints): 4g+tg banks
#define UELE (32 * UBST)         // 4224 uints
#define UHAT_SMEM ((2 * WELE + 2 * XELE + UELE) * 4)   // 99,840 B

__global__ void __launch_bounds__(256)
uhat_tf32_kernel(const float* __restrict__ x, const float* __restrict__ W) {
    extern __shared__ float dsm[];
    float* Wb0 = dsm;
    float* Wb1 = dsm + WELE;
    float* Xb0 = dsm + 2 * WELE;
    float* Xb1 = dsm + 2 * WELE + XELE;
    unsigned int* ubuf = reinterpret_cast<unsigned int*>(dsm + 2 * WELE + 2 * XELE);

    const int t = threadIdx.x, lane = t & 31, w = t >> 5;
    const int g = lane >> 2, tg = lane & 3;
    const int q  = blockIdx.y;          // c-eighth
    const int k0 = blockIdx.x * KPB;
    const int c  = q * 8 + w;           // this warp's class

    auto stage = [&](int k, float* Wd, float* Xd) {
        const float4* wg = reinterpret_cast<const float4*>(
            W + ((size_t)k * Cc + q * 8) * (Oo * Ii));
#pragma unroll
        for (int it = 0; it < 8; it++) {
            int p = it * 256 + t, m = p >> 3, j = p & 7;
            cpa16(&Wd[m * SP + 4 * j], wg + p);
        }
        const float4* xg = reinterpret_cast<const float4*>(x);
        int bb = t >> 3, j = t & 7;
        cpa16(&Xd[bb * SP + 4 * j], xg + ((size_t)bb * Kk + k) * 8 + j);
        cp_commit();
    };

    float s0acc[32];
#pragma unroll
    for (int i = 0; i < 32; i++) s0acc[i] = 0.f;

    stage(k0, Wb0, Xb0);

#pragma unroll
    for (int kk = 0; kk < KPB; kk++) {
        const int k = k0 + kk;
        const int cur = kk & 1;
        if (kk + 1 < KPB) {
            stage(k + 1, cur ? Wb0 : Wb1, cur ? Xb0 : Xb1);
            cp_wait<1>();
        } else {
            cp_wait<0>();
        }
        __syncthreads();
        const float* Wc = cur ? Wb1 : Wb0;
        const float* Xc = cur ? Xb1 : Xb0;

        unsigned int wf[4][4][2];
#pragma unroll
        for (int j = 0; j < 4; j++) {
            const int n0 = w * 32 + j * 8;
#pragma unroll
            for (int ks = 0; ks < 4; ks++) {
                wf[j][ks][0] = to_tf32(Wc[(n0 + g) * SP + ks * 8 + tg]);
                wf[j][ks][1] = to_tf32(Wc[(n0 + g) * SP + ks * 8 + tg + 4]);
            }
        }

#pragma unroll
        for (int mt = 0; mt < 2; mt++) {
            const int mb = mt * 16;
            unsigned int af[4][4];
#pragma unroll
            for (int ks = 0; ks < 4; ks++) {
                af[ks][0] = to_tf32(Xc[(mb + g)     * SP + ks * 8 + tg]);
                af[ks][1] = to_tf32(Xc[(mb + g + 8) * SP + ks * 8 + tg]);
                af[ks][2] = to_tf32(Xc[(mb + g)     * SP + ks * 8 + tg + 4]);
                af[ks][3] = to_tf32(Xc[(mb + g + 8) * SP + ks * 8 + tg + 4]);
            }
#pragma unroll
            for (int j = 0; j < 4; j++) {
                float acc[4] = {0.f, 0.f, 0.f, 0.f};
#pragma unroll
                for (int ks = 0; ks < 4; ks++)
                    mma_tf32(acc, af[ks][0], af[ks][1], af[ks][2], af[ks][3],
                             wf[j][ks][0], wf[j][ks][1]);
                s0acc[(mt * 4 + j) * 4 + 0] += acc[0];
                s0acc[(mt * 4 + j) * 4 + 1] += acc[1];
                s0acc[(mt * 4 + j) * 4 + 2] += acc[2];
                s0acc[(mt * 4 + j) * 4 + 3] += acc[3];
                // STS into padded tile buffer: (4g+tg) banks, conflict-free
                const int ba = mb + g, bb2 = mb + g + 8;
                const int col = w * 16 + 4 * j + tg;
                ubuf[ba  * UBST + col] = packq(acc[0], acc[1]);
                ubuf[bb2 * UBST + col] = packq(acc[2], acc[3]);
            }
        }
        __syncthreads();   // tile complete (also: all reads of cur done)

        // cooperative coalesced flush: warp = one b-row = 512B contiguous
        {
            uint4* gout = reinterpret_cast<uint4*>(
                g_uh + (size_t)k * (Cc * 16) + q * 128);
            const size_t bstride4 = (size_t)Kk * Cc * 4;   // uint4 per b
#pragma unroll
            for (int it = 0; it < 4; it++) {
                int u = it * 256 + t;          // uint4 idx in tile (0..1023)
                int bi = u >> 5, r4 = u & 31;
                uint4 val = *reinterpret_cast<uint4*>(&ubuf[bi * UBST + r4 * 4]);
                gout[(size_t)bi * bstride4 + r4] = val;
            }
        }
        __syncthreads();   // flush reads done before next k's STS overwrite
    }

    // flush s0 partials: plain float2 stores into this k-block's slice
    float* p0 = g_p0 + (size_t)blockIdx.x * BCO;
#pragma unroll
    for (int mt = 0; mt < 2; mt++)
#pragma unroll
        for (int j = 0; j < 4; j++) {
            int ba = mt * 16 + g, bb2 = ba + 8, o = 8 * j + 2 * tg;
            *reinterpret_cast<float2*>(&p0[(ba  * Cc + c) * Oo + o]) =
                make_float2(s0acc[(mt*4+j)*4 + 0], s0acc[(mt*4+j)*4 + 1]);
            *reinterpret_cast<float2*>(&p0[(bb2 * Cc + c) * Oo + o]) =
                make_float2(s0acc[(mt*4+j)*4 + 2], s0acc[(mt*4+j)*4 + 3]);
        }
}

// ---------------- reduce partials + squash (block per (b,c) row) ---------
// grid = B*C = 2048. Warp w sums partials p = w, w+8, ...; smem combine;
// warp 0 squashes. which: 0 -> p0(128)/scale 1/C -> v0; 1 -> p1 -> v1;
// 2 -> p1 -> ext_out.
__global__ void __launch_bounds__(256)
reduce_squash_kernel(int which, float* __restrict__ ext_out) {
    __shared__ float ps[8][Oo];

    const float* part = (which == 0) ? g_p0 : g_p1;
    const int   NP    = (which == 0) ? NKB0 : NKB1;
    float* vout       = (which == 0) ? g_v0 : (which == 1) ? g_v1 : ext_out;
    const float scale = (which == 0) ? (1.0f / Cc) : 1.0f;

    const int lane = threadIdx.x & 31, w = threadIdx.x >> 5;
    const size_t base = (size_t)blockIdx.x * Oo + lane;   // (b,c) row, o=lane

    float a0 = 0.f, a1 = 0.f;
    for (int p = w; p < NP; p += 16) {      // 2 independent chains / warp
        a0 += part[(size_t)p * BCO + base];
        a1 += part[(size_t)(p + 8) * BCO + base];
    }
    ps[w][lane] = a0 + a1;
    __syncthreads();

    if (w == 0) {
        float val = ((ps[0][lane] + ps[1][lane]) + (ps[2][lane] + ps[3][lane]))
                  + ((ps[4][lane] + ps[5][lane]) + (ps[6][lane] + ps[7][lane]));
        val *= scale;
        float sq = val * val;
#pragma unroll
        for (int sh = 16; sh > 0; sh >>= 1) sq += __shfl_xor_sync(~0u, sq, sh);
        float f = (sq / (1.0f + sq)) * rsqrtf(sq + 1e-8f);
        vout[base] = val * f;
    }
}

// ---------------- routing pass: KC=8, u_hat cached in registers ----------
// Thread -> (c, oh): c = 8w + (lane>>2), oh = lane&3 (8 o's = 1 uint4).
// A: 8 independent agreement chains, tiles kept in regs. B: warp w
// softmaxes k=w. C: s-accum from regs (zero loads) -> partial stores.
#define KC3 8
__global__ void __launch_bounds__(256, 3)
route2_kernel(int iter, float* __restrict__ c_out_ext) {
    __shared__ float tbs[KC3][Cc];        // 2 KB
    __shared__ float csm[KC3][Cc];        // 2 KB

    const int t = threadIdx.x, lane = t & 31, w = t >> 5;
    const int c  = w * 8 + (lane >> 2);
    const int oh = lane & 3;
    const int b  = blockIdx.y;
    const int k0 = blockIdx.x * KC3;

    const float* v = iter ? g_v1 : g_v0;

    // v: each thread reads exactly its own 32B (coalesced)
    const float* vp = v + ((size_t)(b * Cc + c)) * Oo + oh * 8;
    float4 va = *reinterpret_cast<const float4*>(vp);
    float4 vb = *reinterpret_cast<const float4*>(vp + 4);
    float vvs[8] = { va.x * QSI, va.y * QSI, va.z * QSI, va.w * QSI,
                     vb.x * QSI, vb.y * QSI, vb.z * QSI, vb.w * QSI };

    // ---- Phase A: load tiles into regs + agreements ----
    uint4 uv[KC3];
#pragma unroll
    for (int kk = 0; kk < KC3; kk++)
        uv[kk] = *reinterpret_cast<const uint4*>(
            &g_uh[(((size_t)b * Kk + k0 + kk) * Cc + c) * 16 + oh * 4]);

#pragma unroll
    for (int kk = 0; kk < KC3; kk++) {
        float uh[8];
        unpack8(uv[kk], uh);
        float ap = 0.f;
#pragma unroll
        for (int j = 0; j < 8; j++) ap = fmaf(uh[j], vvs[j], ap);
        ap += __shfl_xor_sync(~0u, ap, 1);
        ap += __shfl_xor_sync(~0u, ap, 2);       // full sum over o
        if (oh == 0) tbs[kk][c] = ap;
    }
    __syncthreads();

    // ---- Phase B: softmax, warp w handles k = w ----
    {
        const size_t bk = (size_t)b * Kk + k0 + w;
        float tA = tbs[w][lane], tB = tbs[w][lane + 32];
        if (iter) {
            tA += g_b1[bk * Cc + lane];
            tB += g_b1[bk * Cc + lane + 32];
        }
        float eA = __expf(tA), eB = __expf(tB);  // |t| << 1: no max-pass
        float s = eA + eB;
#pragma unroll
        for (int sh = 16; sh > 0; sh >>= 1) s += __shfl_xor_sync(~0u, s, sh);
        float inv = 1.0f / s;                    // exact sum over 64 classes
        float cvA = eA * inv, cvB = eB * inv;
        csm[w][lane]      = cvA;
        csm[w][lane + 32] = cvB;
        if (iter) {
            c_out_ext[bk * Cc + lane]      = cvA;
            c_out_ext[bk * Cc + lane + 32] = cvB;
        } else {
            g_b1[bk * Cc + lane]      = tA;
            g_b1[bk * Cc + lane + 32] = tB;
        }
    }
    __syncthreads();

    // ---- Phase C: s accumulation from registers (zero loads) ----
    float sacc[8];
#pragma unroll
    for (int j = 0; j < 8; j++) sacc[j] = 0.f;
#pragma unroll
    for (int kk = 0; kk < KC3; kk++) {
        float uh[8];
        unpack8(uv[kk], uh);
        float cij = csm[kk][c];
#pragma unroll
        for (int j = 0; j < 8; j++) sacc[j] = fmaf(cij, uh[j], sacc[j]);
    }

    // plain coalesced partial stores (1KB contiguous per warp)
    float* pd = g_p1 + ((size_t)blockIdx.x * Bb + b) * (Cc * Oo)
              + c * Oo + oh * 8;
    *reinterpret_cast<float4*>(pd) =
        make_float4(sacc[0] * QSI, sacc[1] * QSI, sacc[2] * QSI, sacc[3] * QSI);
    *reinterpret_cast<float4*>(pd + 4) =
        make_float4(sacc[4] * QSI, sacc[5] * QSI, sacc[6] * QSI, sacc[7] * QSI);
}

// ---------------- launch -------------------------------------------------
extern "C" void kernel_launch(void* const* d_in, const int* in_sizes, int n_in,
                              void* d_out, int out_size) {
    const float* x = (const float*)d_in[0];   // [B,K,I]
    const float* W = (const float*)d_in[1];   // [K,C,O,I]
    if (n_in >= 2 && in_sizes[0] > in_sizes[1]) {  // defensive: order by size
        const float* tmp = x; x = W; W = tmp;
    }
    float* out   = (float*)d_out;
    float* v_out = out;                 // [B,C,O]
    float* c_out = out + Bb * Cc * Oo;  // [B,K,C]

    cudaFuncSetAttribute(uhat_tf32_kernel,
                         cudaFuncAttributeMaxDynamicSharedMemorySize, UHAT_SMEM);

    uhat_tf32_kernel<<<dim3(NKB0, 8), 256, UHAT_SMEM>>>(x, W);   // u_hat + p0

    reduce_squash_kernel<<<Bb * Cc, 256>>>(0, nullptr);          // v0

    route2_kernel<<<dim3(NKB1, Bb), 256>>>(0, nullptr);          // b1, p1
    reduce_squash_kernel<<<Bb * Cc, 256>>>(1, nullptr);          // v1

    route2_kernel<<<dim3(NKB1, Bb), 256>>>(1, c_out);            // c_ij, p1
    reduce_squash_kernel<<<Bb * Cc, 256>>>(2, v_out);            // v out
}